// round 1
// baseline (speedup 1.0000x reference)
#include <cuda_runtime.h>
#include <cstdint>

#define BATCH 64
#define SEQ   2048
#define HD    64
#define BM    128
#define BN    64
#define NKT   (SEQ / BN)          /* 32 key tiles */
#define KSTR  68                  /* stride%32==4 -> conflict-free 8row x 4col pattern */
#define VSTR  72                  /* stride%32==8 -> conflict-free 4row x 8col pattern */
#define PSTR  68
#define SMEM_FLOATS (BM * PSTR + 2 * BN * KSTR + 2 * BN * VSTR)
#define SMEM_BYTES  (SMEM_FLOATS * 4)

__device__ __forceinline__ uint32_t f2tf(float x) {
    uint32_t u; asm("cvt.rna.tf32.f32 %0, %1;" : "=r"(u) : "f"(x)); return u;
}
__device__ __forceinline__ float ex2f(float x) {
    float y; asm("ex2.approx.ftz.f32 %0, %1;" : "=f"(y) : "f"(x)); return y;
}
__device__ __forceinline__ void mma_tf32(float d[4], const uint32_t a[4],
                                         uint32_t b0, uint32_t b1) {
    asm volatile(
        "mma.sync.aligned.m16n8k8.row.col.f32.tf32.tf32.f32 "
        "{%0,%1,%2,%3}, {%4,%5,%6,%7}, {%8,%9}, {%0,%1,%2,%3};\n"
        : "+f"(d[0]), "+f"(d[1]), "+f"(d[2]), "+f"(d[3])
        : "r"(a[0]), "r"(a[1]), "r"(a[2]), "r"(a[3]), "r"(b0), "r"(b1));
}
__device__ __forceinline__ void cp16(uint32_t saddr, const void* gaddr) {
    asm volatile("cp.async.cg.shared.global [%0], [%1], 16;\n"
                 :: "r"(saddr), "l"(gaddr) : "memory");
}

__device__ __forceinline__ void prefetch_tile(const float* __restrict__ gK,
                                              const float* __restrict__ gV,
                                              float* sKbuf, float* sVbuf, int tid) {
    // 64x64 floats per tile = 1024 float4; 256 threads -> 4 each per tile
#pragma unroll
    for (int i = 0; i < 4; i++) {
        int lin = tid + i * 256;
        int row = lin >> 4, c4 = lin & 15;
        cp16((uint32_t)__cvta_generic_to_shared(sKbuf + row * KSTR + c4 * 4),
             gK + row * HD + c4 * 4);
    }
#pragma unroll
    for (int i = 0; i < 4; i++) {
        int lin = tid + i * 256;
        int row = lin >> 4, c4 = lin & 15;
        cp16((uint32_t)__cvta_generic_to_shared(sVbuf + row * VSTR + c4 * 4),
             gV + row * HD + c4 * 4);
    }
}

__global__ void __launch_bounds__(256, 1)
attn_tf32_kernel(const float* __restrict__ Q, const float* __restrict__ K,
                 const float* __restrict__ V, float* __restrict__ O)
{
    extern __shared__ float sm[];
    float* sP = sm;                       // [128][68] : Q staging, then P tiles
    float* sK = sm + BM * PSTR;           // [2][64][68]
    float* sV = sK + 2 * BN * KSTR;       // [2][64][72]

    const int tid  = threadIdx.x;
    const int warp = tid >> 5;
    const int lane = tid & 31;
    const int g = lane >> 2;              // groupID
    const int c = lane & 3;               // threadID_in_group

    const int qt = blockIdx.x;
    const int b  = blockIdx.y;

    const float* Qb = Q + ((size_t)b * SEQ + (size_t)qt * BM) * HD;
    const float* Kb = K + (size_t)b * SEQ * HD;
    const float* Vb = V + (size_t)b * SEQ * HD;
    float*       Ob = O + ((size_t)b * SEQ + (size_t)qt * BM) * HD;

    // ---- prefetch first K/V tile into buffer 0 (get HBM/L2 moving early) ----
    prefetch_tile(Kb, Vb, sK, sV, tid);
    asm volatile("cp.async.commit_group;\n" ::: "memory");

    // ---- stage Q tile (coalesced) into sP ----
#pragma unroll
    for (int i = 0; i < 8; i++) {
        int lin = tid + i * 256;          // float4 index, 2048 total
        int row = lin >> 4, c4 = lin & 15;
        float4 v = *(const float4*)(Qb + row * HD + c4 * 4);
        *(float4*)(sP + row * PSTR + c4 * 4) = v;
    }
    __syncthreads();

    // ---- Q fragments: fold softmax scale * log2(e), split into tf32 hi/lo ----
    const float qscale = 0.125f * 1.4426950408889634f;
    uint32_t qh[8][4], ql[8][4];
#pragma unroll
    for (int ks = 0; ks < 8; ks++) {
        int r0 = warp * 16 + g;
        int cc = ks * 8 + c;
        float q0 = sP[r0 * PSTR + cc] * qscale;
        float q1 = sP[(r0 + 8) * PSTR + cc] * qscale;
        float q2 = sP[r0 * PSTR + cc + 4] * qscale;
        float q3 = sP[(r0 + 8) * PSTR + cc + 4] * qscale;
        qh[ks][0] = f2tf(q0); ql[ks][0] = f2tf(q0 - __uint_as_float(qh[ks][0]));
        qh[ks][1] = f2tf(q1); ql[ks][1] = f2tf(q1 - __uint_as_float(qh[ks][1]));
        qh[ks][2] = f2tf(q2); ql[ks][2] = f2tf(q2 - __uint_as_float(qh[ks][2]));
        qh[ks][3] = f2tf(q3); ql[ks][3] = f2tf(q3 - __uint_as_float(qh[ks][3]));
    }

    float oacc[8][4];
#pragma unroll
    for (int nt = 0; nt < 8; nt++) {
        oacc[nt][0] = 0.f; oacc[nt][1] = 0.f; oacc[nt][2] = 0.f; oacc[nt][3] = 0.f;
    }
    float mA = -1e30f, mB = -1e30f, lA = 0.f, lB = 0.f;

    for (int kb = 0; kb < NKT; kb++) {
        const int cur = kb & 1;
        if (kb + 1 < NKT) {
            prefetch_tile(Kb + (size_t)(kb + 1) * BN * HD,
                          Vb + (size_t)(kb + 1) * BN * HD,
                          sK + (cur ^ 1) * BN * KSTR,
                          sV + (cur ^ 1) * BN * VSTR, tid);
            asm volatile("cp.async.commit_group;\n" ::: "memory");
            asm volatile("cp.async.wait_group 1;\n" ::: "memory");
        } else {
            asm volatile("cp.async.wait_group 0;\n" ::: "memory");
        }
        __syncthreads();   // current K/V buffer visible to all warps

        const float* Kt = sK + cur * BN * KSTR;
        const float* Vt = sV + cur * BN * VSTR;

        // ---- S = Q K^T (3xTF32: hi*hi + hi*lo + lo*hi) ----
        float sacc[8][4];
#pragma unroll
        for (int nt = 0; nt < 8; nt++) {
            sacc[nt][0] = 0.f; sacc[nt][1] = 0.f; sacc[nt][2] = 0.f; sacc[nt][3] = 0.f;
        }
#pragma unroll
        for (int ks = 0; ks < 8; ks++) {
#pragma unroll
            for (int nt = 0; nt < 8; nt++) {
                float k0 = Kt[(nt * 8 + g) * KSTR + ks * 8 + c];
                float k1 = Kt[(nt * 8 + g) * KSTR + ks * 8 + c + 4];
                uint32_t bh0 = f2tf(k0), bh1 = f2tf(k1);
                uint32_t bl0 = f2tf(k0 - __uint_as_float(bh0));
                uint32_t bl1 = f2tf(k1 - __uint_as_float(bh1));
                mma_tf32(sacc[nt], qh[ks], bh0, bh1);
                mma_tf32(sacc[nt], qh[ks], bl0, bl1);
                mma_tf32(sacc[nt], ql[ks], bh0, bh1);
            }
        }

        // ---- online softmax (base 2; log2e folded into Q) ----
        float mAn = mA, mBn = mB;
#pragma unroll
        for (int nt = 0; nt < 8; nt++) {
            mAn = fmaxf(mAn, fmaxf(sacc[nt][0], sacc[nt][1]));
            mBn = fmaxf(mBn, fmaxf(sacc[nt][2], sacc[nt][3]));
        }
        mAn = fmaxf(mAn, __shfl_xor_sync(0xffffffffu, mAn, 1));
        mAn = fmaxf(mAn, __shfl_xor_sync(0xffffffffu, mAn, 2));
        mBn = fmaxf(mBn, __shfl_xor_sync(0xffffffffu, mBn, 1));
        mBn = fmaxf(mBn, __shfl_xor_sync(0xffffffffu, mBn, 2));

        float aA = ex2f(mA - mAn), aB = ex2f(mB - mBn);
        float sumA = 0.f, sumB = 0.f;
#pragma unroll
        for (int nt = 0; nt < 8; nt++) {
            sacc[nt][0] = ex2f(sacc[nt][0] - mAn); sumA += sacc[nt][0];
            sacc[nt][1] = ex2f(sacc[nt][1] - mAn); sumA += sacc[nt][1];
            sacc[nt][2] = ex2f(sacc[nt][2] - mBn); sumB += sacc[nt][2];
            sacc[nt][3] = ex2f(sacc[nt][3] - mBn); sumB += sacc[nt][3];
        }
        sumA += __shfl_xor_sync(0xffffffffu, sumA, 1);
        sumA += __shfl_xor_sync(0xffffffffu, sumA, 2);
        sumB += __shfl_xor_sync(0xffffffffu, sumB, 1);
        sumB += __shfl_xor_sync(0xffffffffu, sumB, 2);
        lA = lA * aA + sumA; lB = lB * aB + sumB;
        mA = mAn; mB = mBn;
#pragma unroll
        for (int nt = 0; nt < 8; nt++) {
            oacc[nt][0] *= aA; oacc[nt][1] *= aA;
            oacc[nt][2] *= aB; oacc[nt][3] *= aB;
        }

        // ---- P via smem (C-layout -> A-layout), per-warp private rows ----
#pragma unroll
        for (int nt = 0; nt < 8; nt++) {
            int r0 = warp * 16 + g;
            *(float2*)(sP + r0 * PSTR + nt * 8 + 2 * c) =
                make_float2(sacc[nt][0], sacc[nt][1]);
            *(float2*)(sP + (r0 + 8) * PSTR + nt * 8 + 2 * c) =
                make_float2(sacc[nt][2], sacc[nt][3]);
        }
        __syncwarp();

        // ---- O += P V ----
#pragma unroll
        for (int ks = 0; ks < 8; ks++) {
            int r0 = warp * 16 + g;
            int pc = ks * 8 + c;
            uint32_t a[4];
            a[0] = f2tf(sP[r0 * PSTR + pc]);
            a[1] = f2tf(sP[(r0 + 8) * PSTR + pc]);
            a[2] = f2tf(sP[r0 * PSTR + pc + 4]);
            a[3] = f2tf(sP[(r0 + 8) * PSTR + pc + 4]);
#pragma unroll
            for (int nt = 0; nt < 8; nt++) {
                uint32_t b0 = f2tf(Vt[(ks * 8 + c) * VSTR + nt * 8 + g]);
                uint32_t b1 = f2tf(Vt[(ks * 8 + c + 4) * VSTR + nt * 8 + g]);
                mma_tf32(oacc[nt], a, b0, b1);
            }
        }
        __syncthreads();   // all warps done with current buffers before next prefetch overwrites
    }

    // ---- epilogue: normalize and store ----
    float iA = 1.f / lA, iB = 1.f / lB;
#pragma unroll
    for (int nt = 0; nt < 8; nt++) {
        int r0 = warp * 16 + g;
        *(float2*)(Ob + r0 * HD + nt * 8 + 2 * c) =
            make_float2(oacc[nt][0] * iA, oacc[nt][1] * iA);
        *(float2*)(Ob + (r0 + 8) * HD + nt * 8 + 2 * c) =
            make_float2(oacc[nt][2] * iB, oacc[nt][3] * iB);
    }
}

extern "C" void kernel_launch(void* const* d_in, const int* in_sizes, int n_in,
                              void* d_out, int out_size) {
    (void)in_sizes; (void)n_in; (void)out_size;
    const float* Q = (const float*)d_in[0];
    const float* K = (const float*)d_in[1];
    const float* V = (const float*)d_in[2];
    float* O = (float*)d_out;

    cudaFuncSetAttribute(attn_tf32_kernel,
                         cudaFuncAttributeMaxDynamicSharedMemorySize, SMEM_BYTES);
    dim3 grid(SEQ / BM, BATCH);
    attn_tf32_kernel<<<grid, 256, SMEM_BYTES>>>(Q, K, V, O);
}